// round 2
// baseline (speedup 1.0000x reference)
#include <cuda_runtime.h>

// ---------------------------------------------------------------------------
// DCTFreqConv: per 8x8 block: coef = D B D^T (per channel), conv1d(win=3) over
// flattened 64 coefs mixing 64 channels, + bias, then inverse DCT.
// Layout: x (8,64,256,256) f32, conv_w (64,64,3), conv_b (64). out = x shape.
// One CTA handles 2 adjacent spatial blocks (same batch/row), 256 threads.
// ---------------------------------------------------------------------------

#define CH_STR   65536              // 256*256
#define B_STR    (64*65536)

#define WSM_SZ      (3*64*64)       // 12288 floats
#define RAW_OFF     WSM_SZ
#define RAW_STRIDE  4368            // 64*68 + 16 (pad: distinct banks per sample)
#define RAW_SZ      (2*RAW_STRIDE)
#define XC_OFF      (RAW_OFF + RAW_SZ)
#define XC_SZ       (64*68)
#define BIAS_OFF    (XC_OFF + XC_SZ)
#define SMEM_FLOATS (BIAS_OFF + 64)
#define SMEM_BYTES  (SMEM_FLOATS * 4)   // 101760 B -> 2 CTAs/SM

// 8x8 DCT-II matrix (row 0 scaled by 1/sqrt(2)); compile-time so ptxas emits
// FFMA-imm (rt_SMSP=1, 2x tput vs 3-reg FFMA).
__device__ constexpr float DT[8][8] = {
  {0.35355339059327373f, 0.35355339059327373f, 0.35355339059327373f, 0.35355339059327373f,
   0.35355339059327373f, 0.35355339059327373f, 0.35355339059327373f, 0.35355339059327373f},
  {0.49039264020161522f, 0.41573480615127262f, 0.27778511650980114f, 0.09754516100806417f,
  -0.09754516100806417f,-0.27778511650980114f,-0.41573480615127262f,-0.49039264020161522f},
  {0.46193976625564337f, 0.19134171618254492f,-0.19134171618254492f,-0.46193976625564337f,
  -0.46193976625564337f,-0.19134171618254492f, 0.19134171618254492f, 0.46193976625564337f},
  {0.41573480615127262f,-0.09754516100806417f,-0.49039264020161522f,-0.27778511650980114f,
   0.27778511650980114f, 0.49039264020161522f, 0.09754516100806417f,-0.41573480615127262f},
  {0.35355339059327373f,-0.35355339059327373f,-0.35355339059327373f, 0.35355339059327373f,
   0.35355339059327373f,-0.35355339059327373f,-0.35355339059327373f, 0.35355339059327373f},
  {0.27778511650980114f,-0.49039264020161522f, 0.09754516100806417f, 0.41573480615127262f,
  -0.41573480615127262f,-0.09754516100806417f, 0.49039264020161522f,-0.27778511650980114f},
  {0.19134171618254492f,-0.46193976625564337f, 0.46193976625564337f,-0.19134171618254492f,
  -0.19134171618254492f, 0.46193976625564337f,-0.46193976625564337f, 0.19134171618254492f},
  {0.09754516100806417f,-0.27778511650980114f, 0.41573480615127262f,-0.49039264020161522f,
   0.49039264020161522f,-0.41573480615127262f, 0.27778511650980114f,-0.09754516100806417f}
};

// ---- packed f32x2 helpers (Blackwell FFMA2 path; PTX-only per SASS notes) ----
__device__ __forceinline__ unsigned long long pk2(float lo, float hi) {
    unsigned long long r;
    asm("mov.b64 %0, {%1, %2};" : "=l"(r) : "f"(lo), "f"(hi));
    return r;
}
__device__ __forceinline__ void upk2(unsigned long long v, float& lo, float& hi) {
    asm("mov.b64 {%0, %1}, %2;" : "=f"(lo), "=f"(hi) : "l"(v));
}
__device__ __forceinline__ void fma2(unsigned long long& d,
                                     unsigned long long a, unsigned long long b) {
    asm("fma.rn.f32x2 %0, %1, %2, %0;" : "+l"(d) : "l"(a), "l"(b));
}

// Forward DCT: thread owns channel c, computes coef rows k = 2Q, 2Q+1.
// coef[k][l] = sum_m (sum_n D[k][n]*raw[n*8+m]) * D[l][m]
template<int Q>
__device__ __forceinline__ void dct_rows(const float* rawc, float* xcc) {
    constexpr int K0 = 2 * Q, K1 = 2 * Q + 1;
    float t0[8], t1[8];
#pragma unroll
    for (int m = 0; m < 8; m++) { t0[m] = 0.f; t1[m] = 0.f; }
#pragma unroll
    for (int n = 0; n < 8; n++) {
        float4 a = *(const float4*)(rawc + n * 8);
        float4 b = *(const float4*)(rawc + n * 8 + 4);
        float rn[8] = {a.x, a.y, a.z, a.w, b.x, b.y, b.z, b.w};
#pragma unroll
        for (int m = 0; m < 8; m++) {
            t0[m] = fmaf(rn[m], DT[K0][n], t0[m]);
            t1[m] = fmaf(rn[m], DT[K1][n], t1[m]);
        }
    }
    float c0[8], c1[8];
#pragma unroll
    for (int l = 0; l < 8; l++) {
        float a0 = 0.f, a1 = 0.f;
#pragma unroll
        for (int m = 0; m < 8; m++) {
            a0 = fmaf(t0[m], DT[l][m], a0);
            a1 = fmaf(t1[m], DT[l][m], a1);
        }
        c0[l] = a0; c1[l] = a1;
    }
    *(float4*)(xcc + K0 * 8)     = make_float4(c0[0], c0[1], c0[2], c0[3]);
    *(float4*)(xcc + K0 * 8 + 4) = make_float4(c0[4], c0[5], c0[6], c0[7]);
    *(float4*)(xcc + K1 * 8)     = make_float4(c1[0], c1[1], c1[2], c1[3]);
    *(float4*)(xcc + K1 * 8 + 4) = make_float4(c1[4], c1[5], c1[6], c1[7]);
}

// Inverse DCT: thread owns channel c, computes img columns m = 2Q, 2Q+1.
// img[n][m] = sum_k D[k][n] * (sum_l Y[k][l]*D[l][m])
template<int Q>
__device__ __forceinline__ void idct_cols(const float* yc, float* rawc) {
    constexpr int M0 = 2 * Q, M1 = 2 * Q + 1;
    float sA[8], sB[8];
#pragma unroll
    for (int k = 0; k < 8; k++) {
        float4 a = *(const float4*)(yc + k * 8);
        float4 b = *(const float4*)(yc + k * 8 + 4);
        float yk[8] = {a.x, a.y, a.z, a.w, b.x, b.y, b.z, b.w};
        float aA = 0.f, aB = 0.f;
#pragma unroll
        for (int l = 0; l < 8; l++) {
            aA = fmaf(yk[l], DT[l][M0], aA);
            aB = fmaf(yk[l], DT[l][M1], aB);
        }
        sA[k] = aA; sB[k] = aB;
    }
#pragma unroll
    for (int n = 0; n < 8; n++) {
        float iA = 0.f, iB = 0.f;
#pragma unroll
        for (int k = 0; k < 8; k++) {
            iA = fmaf(sA[k], DT[k][n], iA);
            iB = fmaf(sB[k], DT[k][n], iB);
        }
        *(float2*)(rawc + n * 8 + M0) = make_float2(iA, iB);
    }
}

__global__ __launch_bounds__(256, 2)
void dctfreqconv_kernel(const float* __restrict__ x, const float* __restrict__ cw,
                        const float* __restrict__ cb, float* __restrict__ out) {
    extern __shared__ float sm[];
    float* Wsm = sm;                 // [w][in_ch][out_ch]  (3*64*64)
    float* Raw = sm + RAW_OFF;       // 2 samples x 64ch x 68 (8x8 block, padded)
    float* Xc  = sm + XC_OFF;        // 64ch x 68 : DCT coefs (t-padded), then Y
    float* Bs  = sm + BIAS_OFF;

    const int tid = threadIdx.x;
    const int bidx = blockIdx.x;
    const int batch = bidx >> 9;
    const int rem = bidx & 511;
    const int bi = rem >> 4;         // block row 0..31
    const int jp = rem & 15;         // block-col pair 0..15

    const int gbase = batch * B_STR + bi * 8 * 256 + jp * 16;

    // ---- stage input (2 samples, 128B-coalesced rows) ----
#pragma unroll
    for (int it = 0; it < 8; it++) {
        int f4 = it * 256 + tid;             // 2048 float4s
        int c  = f4 >> 5;
        int r  = (f4 >> 2) & 7;
        int q4 = f4 & 3;
        float4 v = *(const float4*)(x + gbase + c * CH_STR + r * 256 + q4 * 4);
        int s = q4 >> 1, mc = q4 & 1;
        *(float4*)(Raw + s * RAW_STRIDE + c * 68 + r * 8 + mc * 4) = v;
    }
    // ---- stage weights transposed to [w][i][o] ----
#pragma unroll 4
    for (int it = 0; it < 48; it++) {
        int e = it * 256 + tid;              // 12288
        int o = e / 192;
        int rw = e - o * 192;
        int ic = rw / 3;
        int w = rw - ic * 3;
        Wsm[(w * 64 + ic) * 64 + o] = cw[e];
    }
    if (tid < 64) Bs[tid] = cb[tid];
    __syncthreads();

    const int q   = tid >> 6;                // warp-uniform
    const int c   = tid & 63;
    const int ty4 = (tid >> 4) * 4;          // output-channel tile base (0..60)
    const int tx4 = (tid & 15) * 4;          // t tile base (0..60)

    for (int s = 0; s < 2; s++) {
        // ---- forward DCT (FFMA-imm) ----
        {
            const float* rawc = Raw + s * RAW_STRIDE + c * 68;
            float* xcc = Xc + c * 68;
            switch (q) {
                case 0: dct_rows<0>(rawc, xcc); break;
                case 1: dct_rows<1>(rawc, xcc); break;
                case 2: dct_rows<2>(rawc, xcc); break;
                default: dct_rows<3>(rawc, xcc); break;
            }
            if (q == 0) *(float4*)(Xc + c * 68 + 64) = make_float4(0.f, 0.f, 0.f, 0.f);
        }
        __syncthreads();

        // ---- conv: Y[o][t] = sum_{i,w} W[o][i][w] * Xc[i][t+w]  (FFMA2) ----
        unsigned long long acc[4][2];
#pragma unroll
        for (int bb = 0; bb < 4; bb++) { acc[bb][0] = 0ull; acc[bb][1] = 0ull; }

#pragma unroll 4
        for (int i = 0; i < 64; i++) {
            const float* xr = Xc + i * 68 + tx4;
            float4 xa = *(const float4*)xr;
            float2 xb = *(const float2*)(xr + 4);
            unsigned long long xd[6] = {
                pk2(xa.x, xa.x), pk2(xa.y, xa.y), pk2(xa.z, xa.z),
                pk2(xa.w, xa.w), pk2(xb.x, xb.x), pk2(xb.y, xb.y)
            };
#pragma unroll
            for (int w = 0; w < 3; w++) {
                const float* wr = Wsm + (w * 64 + i) * 64 + ty4;
                float2 wv0 = *(const float2*)wr;
                float2 wv1 = *(const float2*)(wr + 2);
                unsigned long long wA = pk2(wv0.x, wv0.y);
                unsigned long long wB = pk2(wv1.x, wv1.y);
#pragma unroll
                for (int bb = 0; bb < 4; bb++) {
                    fma2(acc[bb][0], wA, xd[bb + w]);
                    fma2(acc[bb][1], wB, xd[bb + w]);
                }
            }
        }
        __syncthreads();   // all conv reads of Xc done before overwrite

        // ---- write Y (+bias) back into Xc ----
#pragma unroll
        for (int bb = 0; bb < 4; bb++) {
#pragma unroll
            for (int ap = 0; ap < 2; ap++) {
                float lo, hi;
                upk2(acc[bb][ap], lo, hi);
                int o0 = ty4 + 2 * ap;
                Xc[o0 * 68 + tx4 + bb]       = lo + Bs[o0];
                Xc[(o0 + 1) * 68 + tx4 + bb] = hi + Bs[o0 + 1];
            }
        }
        __syncthreads();

        // ---- inverse DCT (FFMA-imm), img into Raw[s] ----
        {
            float* rawc = Raw + s * RAW_STRIDE + c * 68;
            switch (q) {
                case 0: idct_cols<0>(Xc + c * 68, rawc); break;
                case 1: idct_cols<1>(Xc + c * 68, rawc); break;
                case 2: idct_cols<2>(Xc + c * 68, rawc); break;
                default: idct_cols<3>(Xc + c * 68, rawc); break;
            }
        }
        __syncthreads();
    }

    // ---- store both samples (mirrors load pattern) ----
#pragma unroll
    for (int it = 0; it < 8; it++) {
        int f4 = it * 256 + tid;
        int c2 = f4 >> 5;
        int r  = (f4 >> 2) & 7;
        int q4 = f4 & 3;
        int s = q4 >> 1, mc = q4 & 1;
        float4 v = *(const float4*)(Raw + s * RAW_STRIDE + c2 * 68 + r * 8 + mc * 4);
        *(float4*)(out + gbase + c2 * CH_STR + r * 256 + q4 * 4) = v;
    }
}

extern "C" void kernel_launch(void* const* d_in, const int* in_sizes, int n_in,
                              void* d_out, int out_size) {
    const float* x  = (const float*)d_in[0];
    const float* cw = (const float*)d_in[1];
    const float* cb = (const float*)d_in[2];
    float* out = (float*)d_out;

    cudaFuncSetAttribute(dctfreqconv_kernel,
                         cudaFuncAttributeMaxDynamicSharedMemorySize, SMEM_BYTES);
    // 8 batches * 32 block-rows * 16 block-col-pairs = 4096 CTAs
    dctfreqconv_kernel<<<4096, 256, SMEM_BYTES>>>(x, cw, cb, out);
}

// round 4
// speedup vs baseline: 1.0082x; 1.0082x over previous
#include <cuda_runtime.h>

// ---------------------------------------------------------------------------
// DCTFreqConv: per 8x8 block: coef = D B D^T (per channel), conv1d(win=3) over
// flattened 64 coefs mixing 64 channels, + bias, then inverse DCT.
// One CTA handles 2 adjacent spatial blocks (same batch/row), 256 threads.
// R2: conv rewritten: warp = t-tile (X broadcast), lane = o-pair (W via direct
// LDS.64 into f32x2 operand, zero pack ALU). Cuts conv SMEM traffic ~3x.
// ---------------------------------------------------------------------------

#define CH_STR   65536              // 256*256
#define B_STR    (64*65536)

#define WSM_SZ      (3*64*64)       // 12288 floats
#define RAW_OFF     WSM_SZ
#define RAW_STRIDE  4368            // 64*68 + 16
#define RAW_SZ      (2*RAW_STRIDE)
#define XC_OFF      (RAW_OFF + RAW_SZ)
#define XC_SZ       (64*68)
#define BIAS_OFF    (XC_OFF + XC_SZ)
#define SMEM_FLOATS (BIAS_OFF + 64)
#define SMEM_BYTES  (SMEM_FLOATS * 4)   // 101760 B -> 2 CTAs/SM

// 8x8 DCT-II matrix (row 0 scaled by 1/sqrt(2)); compile-time literals so
// ptxas emits FFMA-imm (rt_SMSP=1).
__device__ constexpr float DT[8][8] = {
  {0.35355339059327373f, 0.35355339059327373f, 0.35355339059327373f, 0.35355339059327373f,
   0.35355339059327373f, 0.35355339059327373f, 0.35355339059327373f, 0.35355339059327373f},
  {0.49039264020161522f, 0.41573480615127262f, 0.27778511650980114f, 0.09754516100806417f,
  -0.09754516100806417f,-0.27778511650980114f,-0.41573480615127262f,-0.49039264020161522f},
  {0.46193976625564337f, 0.19134171618254492f,-0.19134171618254492f,-0.46193976625564337f,
  -0.46193976625564337f,-0.19134171618254492f, 0.19134171618254492f, 0.46193976625564337f},
  {0.41573480615127262f,-0.09754516100806417f,-0.49039264020161522f,-0.27778511650980114f,
   0.27778511650980114f, 0.49039264020161522f, 0.09754516100806417f,-0.41573480615127262f},
  {0.35355339059327373f,-0.35355339059327373f,-0.35355339059327373f, 0.35355339059327373f,
   0.35355339059327373f,-0.35355339059327373f,-0.35355339059327373f, 0.35355339059327373f},
  {0.27778511650980114f,-0.49039264020161522f, 0.09754516100806417f, 0.41573480615127262f,
  -0.41573480615127262f,-0.09754516100806417f, 0.49039264020161522f,-0.27778511650980114f},
  {0.19134171618254492f,-0.46193976625564337f, 0.46193976625564337f,-0.19134171618254492f,
  -0.19134171618254492f, 0.46193976625564337f,-0.46193976625564337f, 0.19134171618254492f},
  {0.09754516100806417f,-0.27778511650980114f, 0.41573480615127262f,-0.49039264020161522f,
   0.49039264020161522f,-0.41573480615127262f, 0.27778511650980114f,-0.09754516100806417f}
};

// ---- packed f32x2 helpers ----
__device__ __forceinline__ unsigned long long pk2dup(float v) {
    unsigned long long r;
    asm("mov.b64 %0, {%1, %1};" : "=l"(r) : "f"(v));
    return r;
}
__device__ __forceinline__ void upk2(unsigned long long v, float& lo, float& hi) {
    asm("mov.b64 {%0, %1}, %2;" : "=f"(lo), "=f"(hi) : "l"(v));
}
__device__ __forceinline__ void fma2(unsigned long long& d,
                                     unsigned long long a, unsigned long long b) {
    asm("fma.rn.f32x2 %0, %1, %2, %0;" : "+l"(d) : "l"(a), "l"(b));
}

// Forward DCT: thread owns channel c, computes coef rows k = 2Q, 2Q+1.
template<int Q>
__device__ __forceinline__ void dct_rows(const float* rawc, float* xcc) {
    constexpr int K0 = 2 * Q, K1 = 2 * Q + 1;
    float t0[8], t1[8];
#pragma unroll
    for (int m = 0; m < 8; m++) { t0[m] = 0.f; t1[m] = 0.f; }
#pragma unroll
    for (int n = 0; n < 8; n++) {
        float4 a = *(const float4*)(rawc + n * 8);
        float4 b = *(const float4*)(rawc + n * 8 + 4);
        float rn[8] = {a.x, a.y, a.z, a.w, b.x, b.y, b.z, b.w};
#pragma unroll
        for (int m = 0; m < 8; m++) {
            t0[m] = fmaf(rn[m], DT[K0][n], t0[m]);
            t1[m] = fmaf(rn[m], DT[K1][n], t1[m]);
        }
    }
    float c0[8], c1[8];
#pragma unroll
    for (int l = 0; l < 8; l++) {
        float a0 = 0.f, a1 = 0.f;
#pragma unroll
        for (int m = 0; m < 8; m++) {
            a0 = fmaf(t0[m], DT[l][m], a0);
            a1 = fmaf(t1[m], DT[l][m], a1);
        }
        c0[l] = a0; c1[l] = a1;
    }
    *(float4*)(xcc + K0 * 8)     = make_float4(c0[0], c0[1], c0[2], c0[3]);
    *(float4*)(xcc + K0 * 8 + 4) = make_float4(c0[4], c0[5], c0[6], c0[7]);
    *(float4*)(xcc + K1 * 8)     = make_float4(c1[0], c1[1], c1[2], c1[3]);
    *(float4*)(xcc + K1 * 8 + 4) = make_float4(c1[4], c1[5], c1[6], c1[7]);
}

// Inverse DCT: thread owns channel c, computes img columns m = 2Q, 2Q+1.
template<int Q>
__device__ __forceinline__ void idct_cols(const float* yc, float* rawc) {
    constexpr int M0 = 2 * Q, M1 = 2 * Q + 1;
    float sA[8], sB[8];
#pragma unroll
    for (int k = 0; k < 8; k++) {
        float4 a = *(const float4*)(yc + k * 8);
        float4 b = *(const float4*)(yc + k * 8 + 4);
        float yk[8] = {a.x, a.y, a.z, a.w, b.x, b.y, b.z, b.w};
        float aA = 0.f, aB = 0.f;
#pragma unroll
        for (int l = 0; l < 8; l++) {
            aA = fmaf(yk[l], DT[l][M0], aA);
            aB = fmaf(yk[l], DT[l][M1], aB);
        }
        sA[k] = aA; sB[k] = aB;
    }
#pragma unroll
    for (int n = 0; n < 8; n++) {
        float iA = 0.f, iB = 0.f;
#pragma unroll
        for (int k = 0; k < 8; k++) {
            iA = fmaf(sA[k], DT[k][n], iA);
            iB = fmaf(sB[k], DT[k][n], iB);
        }
        *(float2*)(rawc + n * 8 + M0) = make_float2(iA, iB);
    }
}

__global__ __launch_bounds__(256, 2)
void dctfreqconv_kernel(const float* __restrict__ x, const float* __restrict__ cw,
                        const float* __restrict__ cb, float* __restrict__ out) {
    extern __shared__ float sm[];
    float* Wsm = sm;                 // [w][in_ch][out_ch]  (3*64*64)
    float* Raw = sm + RAW_OFF;       // 2 samples x 64ch x 68
    float* Xc  = sm + XC_OFF;        // 64ch x 68 : DCT coefs (padded), then Y
    float* Bs  = sm + BIAS_OFF;

    const int tid = threadIdx.x;
    const int bidx = blockIdx.x;
    const int batch = bidx >> 9;
    const int rem = bidx & 511;
    const int bi = rem >> 4;         // block row 0..31
    const int jp = rem & 15;         // block-col pair 0..15

    const int gbase = batch * B_STR + bi * 8 * 256 + jp * 16;

    // ---- stage input (2 samples, 128B-coalesced rows) ----
#pragma unroll
    for (int it = 0; it < 8; it++) {
        int f4 = it * 256 + tid;             // 2048 float4s
        int c  = f4 >> 5;
        int r  = (f4 >> 2) & 7;
        int q4 = f4 & 3;
        float4 v = *(const float4*)(x + gbase + c * CH_STR + r * 256 + q4 * 4);
        int s = q4 >> 1, mc = q4 & 1;
        *(float4*)(Raw + s * RAW_STRIDE + c * 68 + r * 8 + mc * 4) = v;
    }
    // ---- stage weights transposed to [w][i][o] (o pairs contiguous = f32x2) ----
#pragma unroll 4
    for (int it = 0; it < 48; it++) {
        int e = it * 256 + tid;              // 12288
        int o = e / 192;
        int rw = e - o * 192;
        int ic = rw / 3;
        int w = rw - ic * 3;
        Wsm[(w * 64 + ic) * 64 + o] = cw[e];
    }
    if (tid < 64) Bs[tid] = cb[tid];
    __syncthreads();

    const int q  = tid >> 6;                 // warp-uniform (DCT row group)
    const int c  = tid & 63;                 // DCT channel
    const int tt = tid >> 5;                 // conv: warp id = t-tile (0..7)
    const int ol = tid & 31;                 // conv: lane = o-pair (o = 2*ol)
    const float b0 = cb[2 * ol];
    const float b1 = cb[2 * ol + 1];
    const float* wbase = Wsm + 2 * ol;

    for (int s = 0; s < 2; s++) {
        // ---- forward DCT (FFMA-imm) ----
        {
            const float* rawc = Raw + s * RAW_STRIDE + c * 68;
            float* xcc = Xc + c * 68;
            switch (q) {
                case 0: dct_rows<0>(rawc, xcc); break;
                case 1: dct_rows<1>(rawc, xcc); break;
                case 2: dct_rows<2>(rawc, xcc); break;
                default: dct_rows<3>(rawc, xcc); break;
            }
            if (q == 0) *(float4*)(Xc + c * 68 + 64) = make_float4(0.f, 0.f, 0.f, 0.f);
        }
        __syncthreads();

        // ---- conv: Y[o][t] = sum_{i,w} W[o][i][w] * Xc[i][t+w] ----
        // warp tt covers t = 8*tt..8*tt+7 ; lane covers o = 2*ol, 2*ol+1.
        // X segment is identical across the warp -> LDS broadcast (free).
        // W pair loaded directly as 64-bit = f32x2 operand (no pack).
        unsigned long long acc[8];
#pragma unroll
        for (int j = 0; j < 8; j++) acc[j] = 0ull;

        {
            const float* xrow = Xc + 8 * tt;
#pragma unroll 2
            for (int i = 0; i < 64; i++) {
                const float* xr = xrow + i * 68;
                float4 xa = *(const float4*)xr;
                float4 xb = *(const float4*)(xr + 4);
                float2 xc2 = *(const float2*)(xr + 8);
                unsigned long long xd[10] = {
                    pk2dup(xa.x), pk2dup(xa.y), pk2dup(xa.z), pk2dup(xa.w),
                    pk2dup(xb.x), pk2dup(xb.y), pk2dup(xb.z), pk2dup(xb.w),
                    pk2dup(xc2.x), pk2dup(xc2.y)
                };
                const float* wr = wbase + i * 64;
#pragma unroll
                for (int w = 0; w < 3; w++) {
                    unsigned long long wv =
                        *(const unsigned long long*)(wr + w * 4096);
#pragma unroll
                    for (int j = 0; j < 8; j++) fma2(acc[j], wv, xd[j + w]);
                }
            }
        }
        __syncthreads();   // all conv reads of Xc done before overwrite

        // ---- write Y (+bias) back into Xc: rows o=2ol,2ol+1, cols 8tt.. ----
        {
            float lo[8], hi[8];
#pragma unroll
            for (int j = 0; j < 8; j++) {
                upk2(acc[j], lo[j], hi[j]);
                lo[j] += b0; hi[j] += b1;
            }
            float* y0 = Xc + (2 * ol) * 68 + 8 * tt;
            float* y1 = y0 + 68;
            *(float4*)y0       = make_float4(lo[0], lo[1], lo[2], lo[3]);
            *(float4*)(y0 + 4) = make_float4(lo[4], lo[5], lo[6], lo[7]);
            *(float4*)y1       = make_float4(hi[0], hi[1], hi[2], hi[3]);
            *(float4*)(y1 + 4) = make_float4(hi[4], hi[5], hi[6], hi[7]);
        }
        __syncthreads();

        // ---- inverse DCT (FFMA-imm), img into Raw[s] ----
        {
            float* rawc = Raw + s * RAW_STRIDE + c * 68;
            switch (q) {
                case 0: idct_cols<0>(Xc + c * 68, rawc); break;
                case 1: idct_cols<1>(Xc + c * 68, rawc); break;
                case 2: idct_cols<2>(Xc + c * 68, rawc); break;
                default: idct_cols<3>(Xc + c * 68, rawc); break;
            }
        }
        __syncthreads();
    }

    // ---- store both samples (mirrors load pattern) ----
#pragma unroll
    for (int it = 0; it < 8; it++) {
        int f4 = it * 256 + tid;
        int c2 = f4 >> 5;
        int r  = (f4 >> 2) & 7;
        int q4 = f4 & 3;
        int s = q4 >> 1, mc = q4 & 1;
        float4 v = *(const float4*)(Raw + s * RAW_STRIDE + c2 * 68 + r * 8 + mc * 4);
        *(float4*)(out + gbase + c2 * CH_STR + r * 256 + q4 * 4) = v;
    }
}

extern "C" void kernel_launch(void* const* d_in, const int* in_sizes, int n_in,
                              void* d_out, int out_size) {
    const float* x  = (const float*)d_in[0];
    const float* cw = (const float*)d_in[1];
    const float* cb = (const float*)d_in[2];
    float* out = (float*)d_out;

    cudaFuncSetAttribute(dctfreqconv_kernel,
                         cudaFuncAttributeMaxDynamicSharedMemorySize, SMEM_BYTES);
    dctfreqconv_kernel<<<4096, 256, SMEM_BYTES>>>(x, cw, cb, out);
}